// round 17
// baseline (speedup 1.0000x reference)
#include <cuda_runtime.h>
#include <cuda_fp16.h>
#include <math.h>
#include <string.h>

// Problem constants
#define BB 2
#define SS 1024
#define HID 2048
#define NH 32
#define NKV 8
#define HD 64

#define OUT_ELEMS   (BB * SS * HID)             // 4,194,304
#define ATTN_ELEMS  ((size_t)BB * NH * SS * SS) // 67,108,864
#define NROWS       (BB * NH * SS)              // 65,536
#define NKT         16

// Scratch (device globals: no runtime allocation allowed)
__device__ __half g_hidh[(size_t)BB * SS * HID];
__device__ __half g_wqt[(size_t)2048 * 2048];   // [n][k] transposed
__device__ __half g_wkt[(size_t)512 * 2048];
__device__ __half g_wvt[(size_t)512 * 2048];
__device__ __half g_wot[(size_t)2048 * 2048];
__device__ __half g_qh[(size_t)BB * NH * SS * HD];
__device__ __half g_kh[(size_t)BB * NKV * SS * HD];
__device__ __half g_vth[(size_t)BB * NKV * HD * SS];   // V^T: [b,kv][d][s]
__device__ __half g_eh[ATTN_ELEMS];                    // raw exp, half
__device__ __half g_ctxh[(size_t)BB * SS * HID];
__device__ float  g_part[(size_t)NROWS * NKT];
__device__ float  g_inv[NROWS];
__device__ float  g_attn_fallback[ATTN_ELEMS];

// ---------------------------------------------------------------------------
// Helpers
// ---------------------------------------------------------------------------
__device__ __forceinline__ unsigned h2u(__half2 h) {
    unsigned u; memcpy(&u, &h, 4); return u;
}
__device__ __forceinline__ __half2 u2h(unsigned u) {
    __half2 h; memcpy(&h, &u, 4); return h;
}

__device__ __forceinline__ void mma_f16(float c[4],
                                        unsigned a0, unsigned a1, unsigned a2, unsigned a3,
                                        unsigned b0, unsigned b1)
{
    asm volatile(
        "mma.sync.aligned.m16n8k16.row.col.f32.f16.f16.f32 "
        "{%0,%1,%2,%3},{%4,%5,%6,%7},{%8,%9},{%0,%1,%2,%3};"
        : "+f"(c[0]), "+f"(c[1]), "+f"(c[2]), "+f"(c[3])
        : "r"(a0), "r"(a1), "r"(a2), "r"(a3), "r"(b0), "r"(b1));
}

__device__ __forceinline__ void cpa16(void* s, const void* g) {
    unsigned sa = (unsigned)__cvta_generic_to_shared(s);
    asm volatile("cp.async.cg.shared.global [%0], [%1], 16;" :: "r"(sa), "l"(g));
}

// ---------------------------------------------------------------------------
// Conversions: hidden fp32->half; weights fp32 [K][N] -> half [N][K].
// ---------------------------------------------------------------------------
__global__ void convh_kernel(const float* __restrict__ in, __half* __restrict__ out)
{
    int i = blockIdx.x * blockDim.x + threadIdx.x;   // one float4
    float4 v = ((const float4*)in)[i];
    __half2* o = (__half2*)out;
    o[2 * i]     = __floats2half2_rn(v.x, v.y);
    o[2 * i + 1] = __floats2half2_rn(v.z, v.w);
}

__global__ void convt_kernel(const float* __restrict__ wq, const float* __restrict__ wk,
                             const float* __restrict__ wv, const float* __restrict__ wo,
                             __half* __restrict__ wqt, __half* __restrict__ wkt,
                             __half* __restrict__ wvt, __half* __restrict__ wot)
{
    __shared__ float tile[32][33];
    const float* src; __half* dst; int N;
    int zz = blockIdx.z;
    if (zz == 0)      { src = wq; dst = wqt; N = 2048; }
    else if (zz == 1) { src = wk; dst = wkt; N = 512;  }
    else if (zz == 2) { src = wv; dst = wvt; N = 512;  }
    else              { src = wo; dst = wot; N = 2048; }
    int n0 = blockIdx.x * 32;
    if (n0 >= N) return;
    int k0 = blockIdx.y * 32;
    for (int r = threadIdx.y; r < 32; r += 8)
        tile[r][threadIdx.x] = src[(size_t)(k0 + r) * N + n0 + threadIdx.x];
    __syncthreads();
    for (int r = threadIdx.y; r < 32; r += 8)
        dst[(size_t)(n0 + r) * 2048 + k0 + threadIdx.x] =
            __float2half_rn(tile[threadIdx.x][r]);
}

// ---------------------------------------------------------------------------
// FP16 GEMM mainloop: 128x128 tile, BK=32 halves, 3-stage cp.async ring.
// ---------------------------------------------------------------------------
#define HST 20
#define HGEMM_SMEM (2 * 3 * 128 * HST * 4)   // 61440 B

__device__ __forceinline__ void hgemm_mainloop(const __half* __restrict__ Ab,
                                               const __half* __restrict__ Wb,
                                               float acc[4][4][4],
                                               unsigned* As, unsigned* Bs)
{
    const int tid = threadIdx.x;
    const int warp = tid >> 5, lane = tid & 31;
    const int g = lane >> 2, t = lane & 3;
    const int wm = warp >> 2, wn = warp & 3;
    const int ntiles = 2048 / 32;

#pragma unroll
    for (int s = 0; s < 2; s++) {
        const int k0 = s * 32;
        unsigned* An = As + s * 128 * HST;
        unsigned* Bn = Bs + s * 128 * HST;
#pragma unroll
        for (int l = 0; l < 2; l++) {
            int idx = tid + l * 256;
            int row = idx >> 2, seg = idx & 3;
            cpa16(&An[row * HST + seg * 4], Ab + (size_t)row * 2048 + k0 + seg * 8);
            cpa16(&Bn[row * HST + seg * 4], Wb + (size_t)row * 2048 + k0 + seg * 8);
        }
        asm volatile("cp.async.commit_group;");
    }

    for (int i = 0; i < ntiles; i++) {
        if (i + 2 < ntiles) {
            const int k0 = (i + 2) * 32;
            unsigned* An = As + ((i + 2) % 3) * 128 * HST;
            unsigned* Bn = Bs + ((i + 2) % 3) * 128 * HST;
#pragma unroll
            for (int l = 0; l < 2; l++) {
                int idx = tid + l * 256;
                int row = idx >> 2, seg = idx & 3;
                cpa16(&An[row * HST + seg * 4], Ab + (size_t)row * 2048 + k0 + seg * 8);
                cpa16(&Bn[row * HST + seg * 4], Wb + (size_t)row * 2048 + k0 + seg * 8);
            }
            asm volatile("cp.async.commit_group;");
            asm volatile("cp.async.wait_group 2;");
        } else if (i + 1 < ntiles) {
            asm volatile("cp.async.wait_group 1;");
        } else {
            asm volatile("cp.async.wait_group 0;");
        }
        __syncthreads();

        const unsigned* Ac = As + (i % 3) * 128 * HST;
        const unsigned* Bc = Bs + (i % 3) * 128 * HST;

#pragma unroll
        for (int kb = 0; kb < 2; kb++) {
            const int ko = kb * 8;
            unsigned a[4][4], b[4][2];
#pragma unroll
            for (int mt = 0; mt < 4; mt++) {
                int rb = wm * 64 + mt * 16;
                a[mt][0] = Ac[(rb + g) * HST + t + ko];
                a[mt][1] = Ac[(rb + g + 8) * HST + t + ko];
                a[mt][2] = Ac[(rb + g) * HST + t + 4 + ko];
                a[mt][3] = Ac[(rb + g + 8) * HST + t + 4 + ko];
            }
#pragma unroll
            for (int nt = 0; nt < 4; nt++) {
                int cb = wn * 32 + nt * 8;
                b[nt][0] = Bc[(cb + g) * HST + t + ko];
                b[nt][1] = Bc[(cb + g) * HST + t + 4 + ko];
            }
#pragma unroll
            for (int mt = 0; mt < 4; mt++)
#pragma unroll
                for (int nt = 0; nt < 4; nt++)
                    mma_f16(acc[mt][nt], a[mt][0], a[mt][1], a[mt][2], a[mt][3],
                            b[nt][0], b[nt][1]);
        }
        __syncthreads();
    }
}

// ---------------------------------------------------------------------------
// Fused QKV projection (fp16): grid (24, 16). q,k -> half (b,h,s,d);
// v -> half TRANSPOSED (b,kv,d,s).
// ---------------------------------------------------------------------------
__global__ __launch_bounds__(256, 2)
void qkv_kernel(const __half* __restrict__ hid,
                const __half* __restrict__ wqt, const __half* __restrict__ wkt,
                const __half* __restrict__ wvt,
                __half* __restrict__ qo, __half* __restrict__ ko,
                __half* __restrict__ vto)
{
    extern __shared__ unsigned hsm[];
    unsigned* As = hsm;
    unsigned* Bs = hsm + 3 * 128 * HST;

    const int bn = blockIdx.x, bm = blockIdx.y;
    const __half* W; int bl, outk;
    if (bn < 16)      { W = wqt; bl = bn;      outk = 0; }
    else if (bn < 20) { W = wkt; bl = bn - 16; outk = 1; }
    else              { W = wvt; bl = bn - 20; outk = 2; }

    const __half* Ab = hid + (size_t)bm * 128 * 2048;
    const __half* Wb = W + (size_t)bl * 128 * 2048;

    float acc[4][4][4];
#pragma unroll
    for (int i = 0; i < 4; i++)
#pragma unroll
        for (int j = 0; j < 4; j++)
#pragma unroll
            for (int r = 0; r < 4; r++) acc[i][j][r] = 0.f;

    hgemm_mainloop(Ab, Wb, acc, As, Bs);

    const int tid = threadIdx.x;
    const int warp = tid >> 5, lane = tid & 31;
    const int g = lane >> 2, t = lane & 3;
    const int wm = warp >> 2, wn = warp & 3;

#pragma unroll
    for (int mt = 0; mt < 4; mt++)
#pragma unroll
        for (int nt = 0; nt < 4; nt++)
#pragma unroll
            for (int ri = 0; ri < 4; ri++) {
                int r = wm * 64 + mt * 16 + g + ((ri >= 2) ? 8 : 0);
                int c = wn * 32 + nt * 8 + 2 * t + (ri & 1);
                int m = bm * 128 + r, n = bl * 128 + c;
                int b_ = m >> 10, s = m & 1023;
                int head = n >> 6, dd = n & 63;
                __half hv = __float2half_rn(acc[mt][nt][ri]);
                if (outk == 0)
                    qo[(((size_t)b_ * NH + head) * SS + s) * HD + dd] = hv;
                else if (outk == 1)
                    ko[(((size_t)b_ * NKV + head) * SS + s) * HD + dd] = hv;
                else
                    vto[(((size_t)b_ * NKV + head) * HD + dd) * SS + s] = hv;
            }
}

// ---------------------------------------------------------------------------
// Out projection (fp16): out[m][n] = ctxh @ wot.
// ---------------------------------------------------------------------------
__global__ __launch_bounds__(256, 2)
void gemm_kernel(const __half* __restrict__ A, const __half* __restrict__ W,
                 float* __restrict__ C)
{
    extern __shared__ unsigned hsm[];
    unsigned* As = hsm;
    unsigned* Bs = hsm + 3 * 128 * HST;

    const int bn = blockIdx.x, bm = blockIdx.y;
    const __half* Ab = A + (size_t)bm * 128 * 2048;
    const __half* Wb = W + (size_t)bn * 128 * 2048;

    float acc[4][4][4];
#pragma unroll
    for (int i = 0; i < 4; i++)
#pragma unroll
        for (int j = 0; j < 4; j++)
#pragma unroll
            for (int r = 0; r < 4; r++) acc[i][j][r] = 0.f;

    hgemm_mainloop(Ab, Wb, acc, As, Bs);

    const int tid = threadIdx.x;
    const int warp = tid >> 5, lane = tid & 31;
    const int g = lane >> 2, t = lane & 3;
    const int wm = warp >> 2, wn = warp & 3;

#pragma unroll
    for (int mt = 0; mt < 4; mt++)
#pragma unroll
        for (int nt = 0; nt < 4; nt++)
#pragma unroll
            for (int ri = 0; ri < 4; ri++) {
                int r = wm * 64 + mt * 16 + g + ((ri >= 2) ? 8 : 0);
                int c = wn * 32 + nt * 8 + 2 * t + (ri & 1);
                int m = bm * 128 + r, n = bn * 128 + c;
                C[(size_t)m * 2048 + n] = acc[mt][nt][ri];
            }
}

// ---------------------------------------------------------------------------
// RoPE, vectorized half2.
// ---------------------------------------------------------------------------
#define NROWSQ (BB * NH * SS)
#define NROWSK (BB * NKV * SS)

__global__ void rope_kernel(__half* __restrict__ qb, __half* __restrict__ kb,
                            const float* __restrict__ cosb,
                            const float* __restrict__ sinb)
{
    int idx = blockIdx.x * blockDim.x + threadIdx.x;
    int row = idx >> 4;
    int dd = idx & 15;                    // half2 index within first 32 dims
    __half* buf; int r;
    if (row < NROWSQ) { buf = qb; r = row; }
    else              { buf = kb; r = row - NROWSQ; }
    int s = r & (SS - 1);
    __half2* b2 = (__half2*)(buf + (size_t)r * HD);
    float2 x1 = __half22float2(b2[dd]);
    float2 x2 = __half22float2(b2[16 + dd]);
    const float2* c2 = (const float2*)(cosb + s * HD);
    const float2* s2 = (const float2*)(sinb + s * HD);
    float2 c1 = c2[dd], cc2 = c2[16 + dd];
    float2 s1 = s2[dd], ss2 = s2[16 + dd];
    b2[dd]      = __floats2half2_rn(x1.x * c1.x - x2.x * s1.x,
                                    x1.y * c1.y - x2.y * s1.y);
    b2[16 + dd] = __floats2half2_rn(x2.x * cc2.x + x1.x * ss2.x,
                                    x2.y * cc2.y + x1.y * ss2.y);
}

// ---------------------------------------------------------------------------
// Scores (fp16): e = exp((Q.K)/8) masked. Causal tiles -> HALF e to g_eh
// (no attn write). Masked tiles -> zero-fill fp32 attn (required output).
// ---------------------------------------------------------------------------
#define SST 36
#define EST 68

__global__ __launch_bounds__(256)
void scores_kernel(const __half* __restrict__ q, const __half* __restrict__ k,
                   const float* __restrict__ mask, float* __restrict__ attn,
                   __half* __restrict__ eh, float* __restrict__ part)
{
    __shared__ __align__(16) unsigned QK[2 * 64 * SST];   // 18432 B
    unsigned* Qs = QK;
    unsigned* Ks = QK + 64 * SST;

    const int kt = blockIdx.x, qt = blockIdx.y, z = blockIdx.z;
    const int b = z >> 5, h = z & 31, kvh = h >> 2;
    const int tid = threadIdx.x;

    if (kt > qt) { // fully masked tile -> zeros into fp32 attn output
        float* outp = attn + ((size_t)z * SS + qt * 64) * SS + kt * 64;
        float4 zero = make_float4(0.f, 0.f, 0.f, 0.f);
#pragma unroll
        for (int i = 0; i < 4; i++) {
            int idx = tid + i * 256;
            int r = idx >> 4, c = (idx & 15) * 4;
            *(float4*)(outp + (size_t)r * SS + c) = zero;
        }
        return;
    }

    const __half* Q  = q + ((size_t)z * SS + qt * 64) * HD;
    const __half* Kp = k + ((size_t)(b * NKV + kvh) * SS + kt * 64) * HD;

#pragma unroll
    for (int l = 0; l < 4; l++) {
        int idx = tid + l * 256;            // 0..1023
        int isK = idx >> 9;
        int r = (idx >> 3) & 63, seg = idx & 7;
        const __half* src = (isK ? Kp : Q) + (size_t)r * HD + seg * 8;
        unsigned* dstb = isK ? Ks : Qs;
        cpa16(&dstb[r * SST + seg * 4], src);
    }
    asm volatile("cp.async.commit_group;");
    asm volatile("cp.async.wait_group 0;");
    __syncthreads();

    const int warp = tid >> 5, lane = tid & 31;
    const int g = lane >> 2, t = lane & 3;
    const int wm = warp >> 2, wn = warp & 3;

    float acc[2][2][4];
#pragma unroll
    for (int i = 0; i < 2; i++)
#pragma unroll
        for (int j = 0; j < 2; j++)
#pragma unroll
            for (int r = 0; r < 4; r++) acc[i][j][r] = 0.f;

#pragma unroll
    for (int kb = 0; kb < 4; kb++) {
        const int ko = kb * 8;
        unsigned a[2][4], bf[2][2];
#pragma unroll
        for (int mt = 0; mt < 2; mt++) {
            int rb = wm * 32 + mt * 16;
            a[mt][0] = Qs[(rb + g) * SST + t + ko];
            a[mt][1] = Qs[(rb + g + 8) * SST + t + ko];
            a[mt][2] = Qs[(rb + g) * SST + t + 4 + ko];
            a[mt][3] = Qs[(rb + g + 8) * SST + t + 4 + ko];
        }
#pragma unroll
        for (int nt = 0; nt < 2; nt++) {
            int cb = wn * 16 + nt * 8;
            bf[nt][0] = Ks[(cb + g) * SST + t + ko];
            bf[nt][1] = Ks[(cb + g) * SST + t + 4 + ko];
        }
#pragma unroll
        for (int mt = 0; mt < 2; mt++)
#pragma unroll
            for (int nt = 0; nt < 2; nt++)
                mma_f16(acc[mt][nt], a[mt][0], a[mt][1], a[mt][2], a[mt][3],
                        bf[nt][0], bf[nt][1]);
    }
    __syncthreads();

    // ---- stage fp32 e into dead smem ----
    float* Es = (float*)QK;          // 64 x EST floats = 17408 B <= 18432
#pragma unroll
    for (int mt = 0; mt < 2; mt++)
#pragma unroll
        for (int nt = 0; nt < 2; nt++)
#pragma unroll
            for (int ri = 0; ri < 4; ri++) {
                int r = wm * 32 + mt * 16 + g + ((ri >= 2) ? 8 : 0);
                int c = wn * 16 + nt * 8 + 2 * t + (ri & 1);
                int qg = qt * 64 + r, kg = kt * 64 + c;
                bool ok = (kg <= qg) && (mask[b * SS + kg] == 1.0f);
                Es[r * EST + c] = ok ? __expf(acc[mt][nt][ri] * 0.125f) : 0.f;
            }
    __syncthreads();

    // ---- half e store (coalesced, 4 threads/row x 32B) + partial sums ----
    {
        const int srow = tid >> 2, q4 = tid & 3;
        const float* src = Es + srow * EST + q4 * 16;
        __half* dst = eh + ((size_t)z * SS + qt * 64 + srow) * SS + kt * 64 + q4 * 16;
        float s = 0.f;
        unsigned pk[8];
#pragma unroll
        for (int p = 0; p < 8; p++) {
            float e0 = src[2 * p], e1 = src[2 * p + 1];
            s += e0 + e1;
            pk[p] = h2u(__floats2half2_rn(e0, e1));
        }
        *(uint4*)dst       = make_uint4(pk[0], pk[1], pk[2], pk[3]);
        *(uint4*)(dst + 8) = make_uint4(pk[4], pk[5], pk[6], pk[7]);
        s += __shfl_xor_sync(0xffffffffu, s, 1);
        s += __shfl_xor_sync(0xffffffffu, s, 2);
        if (q4 == 0)
            part[((size_t)z * SS + qt * 64 + srow) * NKT + kt] = s;
    }
}

// ---------------------------------------------------------------------------
// Combine partial sums -> 1/rowsum.
// ---------------------------------------------------------------------------
__global__ void combine_kernel(const float* __restrict__ part,
                               float* __restrict__ inv)
{
    int row = blockIdx.x * blockDim.x + threadIdx.x;
    if (row >= NROWS) return;
    int qt = (row & (SS - 1)) >> 6;
    float s = 0.f;
    for (int kt = 0; kt <= qt; kt++) s += part[(size_t)row * NKT + kt];
    inv[row] = 1.0f / s;
}

// ---------------------------------------------------------------------------
// ctx (fp16): cp.async HALF e + half V^T double-buffered. Per tile:
// normalize pass writes the ONLY fp32 attn (causal region) and stores
// normalized half2 into Phw; fp16 mma P@V. FULL 64-col tiles loaded
// (seg 0..7 -> 128 bytes/row), fixing the R15 half-tile bug.
// ---------------------------------------------------------------------------
#define PSW  36
#define VSW  36
#define PHW  36
#define CTX_SMEM ((2 * 64 * PSW + 2 * 64 * VSW + 64 * PHW + 64) * 4)

__global__ __launch_bounds__(256)
void ctx_kernel(const __half* __restrict__ eh, float* __restrict__ attn,
                const __half* __restrict__ vt, const float* __restrict__ inv,
                __half* __restrict__ ctxh)
{
    extern __shared__ unsigned usm[];
    unsigned* Psm  = usm;                      // 2 x 64 x PSW half2
    unsigned* Vsm  = usm + 2 * 64 * PSW;       // 2 x 64 x VSW half2
    unsigned* Phw  = Vsm + 2 * 64 * VSW;       // 64 x PHW half2 (norm. P)
    float*    invs = (float*)(Phw + 64 * PHW); // 64

    const int qt = 15 - blockIdx.x;
    const int z  = blockIdx.y;
    const int b = z >> 5, h = z & 31, kvh = h >> 2;
    const int tid = threadIdx.x;
    const int warp = tid >> 5, lane = tid & 31;
    const int g = lane >> 2, t = lane & 3;
    const int wm = warp >> 2, wn = warp & 3;

    const __half* E = eh + ((size_t)z * SS + qt * 64) * SS;
    float* P = attn + ((size_t)z * SS + qt * 64) * SS;
    const __half* V = vt + (size_t)(b * NKV + kvh) * HD * SS;   // [d][s]
    const int nkt = qt + 1;

    if (tid < 64) invs[tid] = inv[(size_t)z * SS + qt * 64 + tid];

    // prologue: tile 0 (E: 64 rows x 64 halves; V^T: 64 d x 64 s halves)
    {
#pragma unroll
        for (int l = 0; l < 4; l++) {
            int idx = tid + l * 256;            // 0..1023
            int isV = idx >> 9;                 // first 512: E, next 512: V
            int row = (idx >> 3) & 63, seg = idx & 7;
            if (!isV)
                cpa16(&Psm[row * PSW + seg * 4], E + (size_t)row * SS + seg * 8);
            else
                cpa16(&Vsm[row * VSW + seg * 4], V + (size_t)row * SS + seg * 8);
        }
        asm volatile("cp.async.commit_group;");
    }

    float acc[2][2][4];
#pragma unroll
    for (int i = 0; i < 2; i++)
#pragma unroll
        for (int j = 0; j < 2; j++)
#pragma unroll
            for (int r = 0; r < 4; r++) acc[i][j][r] = 0.f;

    for (int kt = 0; kt < nkt; kt++) {
        if (kt + 1 < nkt) {
            unsigned* Pn = Psm + ((kt + 1) & 1) * 64 * PSW;
            unsigned* Vn = Vsm + ((kt + 1) & 1) * 64 * VSW;
            const __half* Eg = E + (size_t)(kt + 1) * 64;
            const __half* Vg = V + (size_t)(kt + 1) * 64;
#pragma unroll
            for (int l = 0; l < 4; l++) {
                int idx = tid + l * 256;
                int isV = idx >> 9;
                int row = (idx >> 3) & 63, seg = idx & 7;
                if (!isV)
                    cpa16(&Pn[row * PSW + seg * 4], Eg + (size_t)row * SS + seg * 8);
                else
                    cpa16(&Vn[row * VSW + seg * 4], Vg + (size_t)row * SS + seg * 8);
            }
            asm volatile("cp.async.commit_group;");
            asm volatile("cp.async.wait_group 1;");
        } else {
            asm volatile("cp.async.wait_group 0;");
        }
        __syncthreads();

        const unsigned* Pc = Psm + (kt & 1) * 64 * PSW;
        const unsigned* Vc = Vsm + (kt & 1) * 64 * VSW;

        // normalize: write fp32 attn (the only causal write) + half2 to Phw
        {
            const int srow = tid >> 2, q4 = tid & 3;   // 4 threads/row
            float iv = invs[srow];
            float* dst = P + (size_t)srow * SS + kt * 64 + q4 * 16;
#pragma unroll
            for (int jj = 0; jj < 4; jj++) {
                unsigned u0 = Pc[srow * PSW + q4 * 8 + jj * 2];
                unsigned u1 = Pc[srow * PSW + q4 * 8 + jj * 2 + 1];
                float2 f0 = __half22float2(u2h(u0));
                float2 f1 = __half22float2(u2h(u1));
                float4 o = make_float4(f0.x * iv, f0.y * iv, f1.x * iv, f1.y * iv);
                *(float4*)(dst + jj * 4) = o;
                Phw[srow * PHW + q4 * 8 + jj * 2]     = h2u(__floats2half2_rn(o.x, o.y));
                Phw[srow * PHW + q4 * 8 + jj * 2 + 1] = h2u(__floats2half2_rn(o.z, o.w));
            }
        }
        __syncthreads();

        // ctx += Pn_tile . V_tile (fp16 mma, fp32 accumulate)
#pragma unroll
        for (int kb = 0; kb < 4; kb++) {
            const int ko = kb * 8;
            unsigned a[2][4], bf[2][2];
#pragma unroll
            for (int mt = 0; mt < 2; mt++) {
                int rb = wm * 32 + mt * 16;
                a[mt][0] = Phw[(rb + g) * PHW + t + ko];
                a[mt][1] = Phw[(rb + g + 8) * PHW + t + ko];
                a[mt][2] = Phw[(rb + g) * PHW + t + 4 + ko];
                a[mt][3] = Phw[(rb + g + 8) * PHW + t + 4 + ko];
            }
#pragma unroll
            for (int nt = 0; nt < 2; nt++) {
                int cb = wn * 16 + nt * 8;
                bf[nt][0] = Vc[(cb + g) * VSW + t + ko];
                bf[nt][1] = Vc[(cb + g) * VSW + t + 4 + ko];
            }
#pragma unroll
            for (int mt = 0; mt < 2; mt++)
#pragma unroll
                for (int nt = 0; nt < 2; nt++)
                    mma_f16(acc[mt][nt], a[mt][0], a[mt][1], a[mt][2], a[mt][3],
                            bf[nt][0], bf[nt][1]);
        }
        __syncthreads();
    }

#pragma unroll
    for (int mt = 0; mt < 2; mt++)
#pragma unroll
        for (int nt = 0; nt < 2; nt++)
#pragma unroll
            for (int ri = 0; ri < 4; ri++) {
                int r = wm * 32 + mt * 16 + g + ((ri >= 2) ? 8 : 0);
                int c = wn * 16 + nt * 8 + 2 * t + (ri & 1);
                int qg = qt * 64 + r;
                ctxh[((size_t)b * SS + qg) * HID + h * HD + c] =
                    __float2half_rn(acc[mt][nt][ri]);
            }
}

// ---------------------------------------------------------------------------
extern "C" void kernel_launch(void* const* d_in, const int* in_sizes, int n_in,
                              void* d_out, int out_size)
{
    const float* hidden = (const float*)d_in[0];
    const float* mask   = (const float*)d_in[1];
    const float* cosb   = (const float*)d_in[2];
    const float* sinb   = (const float*)d_in[3];
    const float* wq     = (const float*)d_in[4];
    const float* wk     = (const float*)d_in[5];
    const float* wv     = (const float*)d_in[6];
    const float* wo     = (const float*)d_in[7];

    float* outp = (float*)d_out;

    __half *hidh, *wqt, *wkt, *wvt, *wot, *qh, *kh, *vth, *ehp, *ctxh;
    float *pp, *ip;
    cudaGetSymbolAddress((void**)&hidh, g_hidh);
    cudaGetSymbolAddress((void**)&wqt, g_wqt);
    cudaGetSymbolAddress((void**)&wkt, g_wkt);
    cudaGetSymbolAddress((void**)&wvt, g_wvt);
    cudaGetSymbolAddress((void**)&wot, g_wot);
    cudaGetSymbolAddress((void**)&qh, g_qh);
    cudaGetSymbolAddress((void**)&kh, g_kh);
    cudaGetSymbolAddress((void**)&vth, g_vth);
    cudaGetSymbolAddress((void**)&ehp, g_eh);
    cudaGetSymbolAddress((void**)&ctxh, g_ctxh);
    cudaGetSymbolAddress((void**)&pp, g_part);
    cudaGetSymbolAddress((void**)&ip, g_inv);

    float* attnp;
    if ((size_t)out_size >= OUT_ELEMS + ATTN_ELEMS) {
        attnp = outp + OUT_ELEMS;
    } else {
        cudaGetSymbolAddress((void**)&attnp, g_attn_fallback);
    }

    cudaFuncSetAttribute(qkv_kernel,
                         cudaFuncAttributeMaxDynamicSharedMemorySize, HGEMM_SMEM);
    cudaFuncSetAttribute(gemm_kernel,
                         cudaFuncAttributeMaxDynamicSharedMemorySize, HGEMM_SMEM);
    cudaFuncSetAttribute(ctx_kernel,
                         cudaFuncAttributeMaxDynamicSharedMemorySize, CTX_SMEM);

    // 0) conversions
    convh_kernel<<<(BB * SS * HID / 4) / 256, 256>>>(hidden, hidh);
    convt_kernel<<<dim3(64, 64, 4), dim3(32, 8)>>>(wq, wk, wv, wo,
                                                   wqt, wkt, wvt, wot);

    // 1) fused QKV projection (fp16); V stored transposed half
    qkv_kernel<<<dim3(24, 16), 256, HGEMM_SMEM>>>(hidh, wqt, wkt, wvt,
                                                  qh, kh, vth);

    // 2) RoPE on half q,k (vectorized)
    rope_kernel<<<((NROWSQ + NROWSK) * 16) / 256, 256>>>(qh, kh, cosb, sinb);

    // 3) scores (fp16) -> half e + zero-fill masked attn + partial sums
    scores_kernel<<<dim3(16, 16, BB * NH), 256>>>(qh, kh, mask, attnp, ehp, pp);

    // 4) combine partials -> 1/rowsum
    combine_kernel<<<NROWS / 256, 256>>>(pp, ip);

    // 5) ctx (fp16): normalize half e -> single fp32 attn write + P@V^T
    ctx_kernel<<<dim3(16, BB * NH), 256, CTX_SMEM>>>(ehp, attnp, vth, ip, ctxh);

    // 6) out = ctxh @ wot (fp16)
    gemm_kernel<<<dim3(16, 16), 256, HGEMM_SMEM>>>(ctxh, wot, outp);
}